// round 12
// baseline (speedup 1.0000x reference)
#include <cuda_runtime.h>
#include <cuda_fp16.h>
#include <math.h>
#include <stdint.h>

#define BB   64
#define TT   512
#define DD   512
#define UU   1024
#define G4   4096
#define NCTA 128

__device__ float  g_xg[(size_t)BB * TT * G4];   // [t][b][4096]
__device__ __align__(16) __half g_xh[(size_t)BB * TT * DD];
__device__ __align__(16) __half g_hh[2][BB * UU];
__device__ volatile unsigned g_gen;  __device__ unsigned g_pad1[31];
__device__ unsigned g_cnt;           __device__ unsigned g_pad2[31];
__device__ volatile unsigned g_genA; __device__ unsigned g_pad3[31];
__device__ unsigned g_cntA;          __device__ unsigned g_pad4[31];
__device__ volatile unsigned g_genB; __device__ unsigned g_pad5[31];
__device__ unsigned g_cntB;          __device__ unsigned g_pad6[31];

// ---------------- helpers ---------------------------------------------------
__device__ __forceinline__ void mma16(float c[4], unsigned a0, unsigned a1,
                                      unsigned a2, unsigned a3,
                                      unsigned b0, unsigned b1) {
    asm volatile(
        "mma.sync.aligned.m16n8k16.row.col.f32.f16.f16.f32 "
        "{%0,%1,%2,%3}, {%4,%5,%6,%7}, {%8,%9}, {%0,%1,%2,%3};"
        : "+f"(c[0]), "+f"(c[1]), "+f"(c[2]), "+f"(c[3])
        : "r"(a0), "r"(a1), "r"(a2), "r"(a3), "r"(b0), "r"(b1));
}
__device__ __forceinline__ uint4 ldsm4(unsigned addr) {
    uint4 r;
    asm volatile("ldmatrix.sync.aligned.m8n8.x4.shared.b16 {%0,%1,%2,%3}, [%4];"
                 : "=r"(r.x), "=r"(r.y), "=r"(r.z), "=r"(r.w) : "r"(addr));
    return r;
}
__device__ __forceinline__ void cp16(unsigned dst, const void* src) {
    asm volatile("cp.async.cg.shared.global [%0], [%1], 16;" :: "r"(dst), "l"(src));
}
__device__ __forceinline__ void cp_commit() {
    asm volatile("cp.async.commit_group;");
}
__device__ __forceinline__ unsigned smem_u32(const void* p) {
    unsigned a;
    asm("{ .reg .u64 t; cvta.to.shared.u64 t, %1; cvt.u32.u64 %0, t; }" : "=r"(a) : "l"(p));
    return a;
}
__device__ __forceinline__ int slot_perm(int slot5) {
    int s = slot5 >> 4, p = slot5 & 15;
    int lcp = (p < 8) ? (p >> 1) : ((p - 8) >> 1);
    int add = (p < 8) ? 0 : 2;
    return 8 * lcp + 4 * s + add + (p & 1);
}
// fast activations (R9/R10-validated)
__device__ __forceinline__ float fsig(float x) {
    float e, r;
    asm("ex2.approx.f32 %0, %1;" : "=f"(e) : "f"(-1.4426950408889634f * x));
    asm("rcp.approx.f32 %0, %1;" : "=f"(r) : "f"(1.0f + e));
    return r;
}
__device__ __forceinline__ float ftanh_(float x) {
    float e, r;
    asm("ex2.approx.f32 %0, %1;" : "=f"(e) : "f"(2.8853900817779268f * x));
    asm("rcp.approx.f32 %0, %1;" : "=f"(r) : "f"(1.0f + e));
    return 1.0f - 2.0f * r;
}

// ========================== conv_x ==========================
__global__ __launch_bounds__(256) void conv_x(const float* __restrict__ x) {
    const size_t n4 = (size_t)BB * TT * DD / 4;
    for (size_t i = (size_t)blockIdx.x * 256 + threadIdx.x; i < n4;
         i += (size_t)gridDim.x * 256) {
        float4 v = reinterpret_cast<const float4*>(x)[i];
        __half2 h01 = __floats2half2_rn(v.x, v.y);
        __half2 h23 = __floats2half2_rn(v.z, v.w);
        uint2 st;
        st.x = *reinterpret_cast<unsigned*>(&h01);
        st.y = *reinterpret_cast<unsigned*>(&h23);
        reinterpret_cast<uint2*>(g_xh)[i] = st;
    }
}

// ================= xg_kernel (R3-validated) =================
#define XG_WT_STRIDE 520
__global__ __launch_bounds__(256) void xg_kernel(
    const float* __restrict__ Wx, const float* __restrict__ bias)
{
    __shared__ __half Wt[32 * XG_WT_STRIDE];
    const int tid = threadIdx.x, warp = tid >> 5, lane = tid & 31;
    const int lr = lane >> 2, lc = lane & 3;
    const int mo = (warp & 3) * 16, no = (warp >> 2) * 16;
    const int ns = blockIdx.x & 127, mg = blockIdx.x >> 7, u0 = ns * 8;

    for (int i = tid; i < 32 * 512; i += 256) {
        int n = i & 31, slotg = i >> 5;
        int k = (slotg & ~31) + slot_perm(slotg & 31);
        int col = (n >> 3) * UU + u0 + (n & 7);
        Wt[n * XG_WT_STRIDE + slotg] = __float2half_rn(Wx[(size_t)k * G4 + col]);
    }
    __syncthreads();
    const unsigned WtB = smem_u32(Wt);
    const unsigned bAddrBase = WtB
        + (unsigned)(no + ((lane >> 4) << 3) + (lane & 7)) * (XG_WT_STRIDE * 2)
        + ((lane >> 3) & 1) * 16;
    float bv[2][2];
#pragma unroll
    for (int j = 0; j < 2; j++) {
        int cl = no + j * 8 + 2 * lc;
        int colg = (cl >> 3) * UU + u0 + (cl & 7);
        bv[j][0] = bias[colg]; bv[j][1] = bias[colg + 1];
    }
    for (int mt = 0; mt < 64; mt++) {
        const int r0 = mg * 4096 + mt * 64;
        const __half* pr0 = g_xh + (size_t)(r0 + mo + lr) * DD + 8 * lc;
        const __half* pr1 = pr0 + 8 * DD;
        float acc[2][4];
#pragma unroll
        for (int j = 0; j < 2; j++)
#pragma unroll
            for (int i = 0; i < 4; i++) acc[j][i] = 0.0f;
        uint4 a0c = *reinterpret_cast<const uint4*>(pr0);
        uint4 a1c = *reinterpret_cast<const uint4*>(pr1);
        uint4 a0n = *reinterpret_cast<const uint4*>(pr0 + 32);
        uint4 a1n = *reinterpret_cast<const uint4*>(pr1 + 32);
#pragma unroll
        for (int kc = 0; kc < 16; kc++) {
            uint4 a0f = make_uint4(0, 0, 0, 0), a1f = a0f;
            if (kc < 14) {
                a0f = *reinterpret_cast<const uint4*>(pr0 + (kc + 2) * 32);
                a1f = *reinterpret_cast<const uint4*>(pr1 + (kc + 2) * 32);
            }
            const unsigned ba = bAddrBase + kc * 64;
            uint4 B0 = ldsm4(ba);
            uint4 B1 = ldsm4(ba + 32);
            mma16(acc[0], a0c.x, a1c.x, a0c.y, a1c.y, B0.x, B0.y);
            mma16(acc[1], a0c.x, a1c.x, a0c.y, a1c.y, B0.z, B0.w);
            mma16(acc[0], a0c.z, a1c.z, a0c.w, a1c.w, B1.x, B1.y);
            mma16(acc[1], a0c.z, a1c.z, a0c.w, a1c.w, B1.z, B1.w);
            a0c = a0n; a1c = a1n; a0n = a0f; a1n = a1f;
        }
        const int rA = r0 + mo + lr, rB = rA + 8;
        const size_t row0 = (size_t)((rA & (TT - 1)) * BB + (rA >> 9)) * G4;
        const size_t row1 = (size_t)((rB & (TT - 1)) * BB + (rB >> 9)) * G4;
#pragma unroll
        for (int j = 0; j < 2; j++) {
            int cl = no + j * 8 + 2 * lc;
            int colg = (cl >> 3) * UU + u0 + (cl & 7);
            *reinterpret_cast<float2*>(&g_xg[row0 + colg]) =
                make_float2(acc[j][0] + bv[j][0], acc[j][1] + bv[j][1]);
            *reinterpret_cast<float2*>(&g_xg[row1 + colg]) =
                make_float2(acc[j][2] + bv[j][0], acc[j][3] + bv[j][1]);
        }
    }
}

// ============== persistent LSTM step kernel (two half-barriers) ==============
#define HS_STRIDE 1032
#define WT_STRIDE 1032
#define WT_BYTES  (32 * WT_STRIDE * 2)
#define HS_BYTES  (64 * HS_STRIDE * 2)
#define SMEM_BYTES (WT_BYTES + HS_BYTES + 64 * 33 * 4 + 512 * 4)

__global__ __launch_bounds__(256) void lstm_persist(
    const float* __restrict__ Wh, const float* __restrict__ h0,
    const float* __restrict__ c0, float* __restrict__ out)
{
    extern __shared__ char smraw[];
    __half* Wt = (__half*)smraw;
    __half* Hs = (__half*)(smraw + WT_BYTES);
    float*  Gs = (float*)(smraw + WT_BYTES + HS_BYTES);
    float*  Cl = Gs + 64 * 33;

    const int tid  = threadIdx.x;
    const int warp = tid >> 5, lane = tid & 31;
    const int lr = lane >> 2, lc = lane & 3;
    const int mo = (warp & 3) * 16;
    const int no = (warp >> 2) * 16;
    const int u0 = blockIdx.x * 8;
    const bool grpA = (blockIdx.x < 64);

    // base generations (read BEFORE init barrier: no step arrivals can exist yet)
    unsigned genA0 = 0, genB0 = 0;
    if (tid == 0) { genA0 = g_genA; genB0 = g_genB; }

    // ---- one-time init ----
    for (int i = tid; i < 32 * 1024; i += 256) {
        int n = i & 31, k = i >> 5;
        int col = (n >> 3) * UU + u0 + (n & 7);
        Wt[n * WT_STRIDE + k] = __float2half_rn(Wh[(size_t)k * G4 + col]);
    }
    for (int i = tid; i < 512; i += 256)
        Cl[i] = c0[(i >> 3) * UU + u0 + (i & 7)];
    for (int i = blockIdx.x * 256 + tid; i < BB * UU; i += NCTA * 256)
        g_hh[0][i] = __float2half_rn(h0[i]);
    __syncthreads();

    if (tid == 0) {                              // full init barrier
        unsigned gen = g_gen;
        __threadfence();
        if (atomicAdd(&g_cnt, 1u) == NCTA - 1u) {
            g_cnt = 0; __threadfence(); g_gen = gen + 1;
        } else {
            while (g_gen == gen) { __nanosleep(32); }
        }
        __threadfence();
    }
    __syncthreads();

    const unsigned HsB = smem_u32(Hs);
    const unsigned WtB = smem_u32(Wt);

    const unsigned aBase = HsB
        + (unsigned)((mo + (lane & 15)) * HS_STRIDE + (lane >> 4) * 8) * 2u;
    const unsigned bBase = WtB
        + (unsigned)((no + ((lane >> 4) << 3) + (lane & 7)) * WT_STRIDE
                     + ((lane >> 3) & 1) * 8) * 2u;

    const int cprow = tid >> 2, cpseg = tid & 3;
    const unsigned cpDst = HsB + (unsigned)(cprow * HS_STRIDE + cpseg * 8) * 2u;

    // cell roles (du pairs) + xg operands for t=0
    const int cm = tid >> 2, cdu = (tid & 3) * 2;
    float2 xa[4];
#pragma unroll
    for (int g = 0; g < 4; g++)
        xa[g] = *reinterpret_cast<const float2*>(
            &g_xg[(size_t)cm * G4 + g * UU + u0 + cdu]);

    for (int t = 0; t < TT; t++) {
        const __half* __restrict__ hc = g_hh[t & 1];
        __half*       __restrict__ hn = g_hh[(t + 1) & 1];
        const __half* cpSrc = hc + (size_t)cprow * UU + cpseg * 8;

        // ---- poll half A (k 0..511 producers), stage half 0 ----
        if (t > 0) {
            if (tid == 0) {
                while (g_genA - genA0 < (unsigned)t) { __nanosleep(20); }
                __threadfence();
            }
            __syncthreads();
        }
#pragma unroll
        for (int kc = 0; kc < 16; kc++)
            cp16(cpDst + kc * 64, cpSrc + kc * 32);
        cp_commit();

        // ---- poll half B (k 512..1023 producers), stage half 1 ----
        if (t > 0) {
            if (tid == 0) {
                while (g_genB - genB0 < (unsigned)t) { __nanosleep(20); }
                __threadfence();
            }
            __syncthreads();
        }
#pragma unroll
        for (int kc = 16; kc < 32; kc++)
            cp16(cpDst + kc * 64, cpSrc + kc * 32);
        cp_commit();

        // 4 independent accumulator chains (R10-validated)
        float acc[2][2][4];
#pragma unroll
        for (int p = 0; p < 2; p++)
#pragma unroll
            for (int j = 0; j < 2; j++)
#pragma unroll
                for (int i = 0; i < 4; i++) acc[p][j][i] = 0.0f;

        // ---- half 1 compute: chunks 0..15 ----
        asm volatile("cp.async.wait_group 1;");
        __syncthreads();
#pragma unroll
        for (int kc = 0; kc < 16; kc++) {
            uint4 A0 = ldsm4(aBase + kc * 64);
            uint4 A1 = ldsm4(aBase + kc * 64 + 32);
            uint4 B0 = ldsm4(bBase + kc * 64);
            uint4 B1 = ldsm4(bBase + kc * 64 + 32);
            mma16(acc[0][0], A0.x, A0.y, A0.z, A0.w, B0.x, B0.y);
            mma16(acc[0][1], A0.x, A0.y, A0.z, A0.w, B0.z, B0.w);
            mma16(acc[1][0], A1.x, A1.y, A1.z, A1.w, B1.x, B1.y);
            mma16(acc[1][1], A1.x, A1.y, A1.z, A1.w, B1.z, B1.w);
        }
        // ---- half 2 compute: chunks 16..31 ----
        asm volatile("cp.async.wait_group 0;");
        __syncthreads();
#pragma unroll
        for (int kc = 16; kc < 32; kc++) {
            uint4 A0 = ldsm4(aBase + kc * 64);
            uint4 A1 = ldsm4(aBase + kc * 64 + 32);
            uint4 B0 = ldsm4(bBase + kc * 64);
            uint4 B1 = ldsm4(bBase + kc * 64 + 32);
            mma16(acc[0][0], A0.x, A0.y, A0.z, A0.w, B0.x, B0.y);
            mma16(acc[0][1], A0.x, A0.y, A0.z, A0.w, B0.z, B0.w);
            mma16(acc[1][0], A1.x, A1.y, A1.z, A1.w, B1.x, B1.y);
            mma16(acc[1][1], A1.x, A1.y, A1.z, A1.w, B1.z, B1.w);
        }

        // ---- epilogue: merge chains into Gs (xg added in cell) ----
        const int rA = mo + lr;
#pragma unroll
        for (int j = 0; j < 2; j++) {
            int cl = no + j * 8 + 2 * lc;
            Gs[rA * 33 + cl]           = acc[0][j][0] + acc[1][j][0];
            Gs[rA * 33 + cl + 1]       = acc[0][j][1] + acc[1][j][1];
            Gs[(rA + 8) * 33 + cl]     = acc[0][j][2] + acc[1][j][2];
            Gs[(rA + 8) * 33 + cl + 1] = acc[0][j][3] + acc[1][j][3];
        }
        __syncthreads();

        // ---- LSTM cell: du pair per thread, __half2 stores ----
        {
            const int gb = cm * 33 + cdu;
            float gi0 = fsig  (Gs[gb]      + xa[0].x), gi1 = fsig  (Gs[gb + 1]  + xa[0].y);
            float gf0 = fsig  (Gs[gb + 8]  + xa[1].x), gf1 = fsig  (Gs[gb + 9]  + xa[1].y);
            float gg0 = ftanh_(Gs[gb + 16] + xa[2].x), gg1 = ftanh_(Gs[gb + 17] + xa[2].y);
            float go0 = fsig  (Gs[gb + 24] + xa[3].x), go1 = fsig  (Gs[gb + 25] + xa[3].y);
            int ce = cm * 8 + cdu;
            float cv0 = gf0 * Cl[ce]     + gi0 * gg0;
            float cv1 = gf1 * Cl[ce + 1] + gi1 * gg1;
            Cl[ce] = cv0; Cl[ce + 1] = cv1;
            float hv0 = go0 * ftanh_(cv0);
            float hv1 = go1 * ftanh_(cv1);
            *reinterpret_cast<__half2*>(&hn[cm * UU + u0 + cdu]) =
                __floats2half2_rn(hv0, hv1);
            if (t == TT - 1)
                *reinterpret_cast<float2*>(&out[cm * UU + u0 + cdu]) =
                    make_float2(hv0, hv1);
        }
        __threadfence();
        __syncthreads();

        // ---- arrive at own group's barrier; prefetch xg[t+1]; NO poll here ----
        if (tid == 0) {
            if (grpA) {
                unsigned g = g_genA;
                if (atomicAdd(&g_cntA, 1u) == 63u) {
                    g_cntA = 0; __threadfence(); g_genA = g + 1;
                }
            } else {
                unsigned g = g_genB;
                if (atomicAdd(&g_cntB, 1u) == 63u) {
                    g_cntB = 0; __threadfence(); g_genB = g + 1;
                }
            }
        }
        if (t + 1 < TT) {
            const size_t base = (size_t)(t + 1) * BB * G4 + (size_t)cm * G4 + u0 + cdu;
#pragma unroll
            for (int g = 0; g < 4; g++)
                xa[g] = *reinterpret_cast<const float2*>(&g_xg[base + g * UU]);
        }
    }
}

// ============================================================================
extern "C" void kernel_launch(void* const* d_in, const int* in_sizes, int n_in,
                              void* d_out, int out_size)
{
    const float* x  = (const float*)d_in[0];
    const float* h0 = (const float*)d_in[1];
    const float* c0 = (const float*)d_in[2];
    const float* Wx = (const float*)d_in[3];
    const float* Wh = (const float*)d_in[4];
    const float* b  = (const float*)d_in[5];
    float* out = (float*)d_out;

    conv_x<<<4096, 256>>>(x);
    xg_kernel<<<1024, 256>>>(Wx, b);

    cudaFuncSetAttribute(lstm_persist, cudaFuncAttributeMaxDynamicSharedMemorySize,
                         SMEM_BYTES);
    lstm_persist<<<NCTA, 256, SMEM_BYTES>>>(Wh, h0, c0, out);

    (void)in_sizes; (void)n_in; (void)out_size;
}

// round 13
// speedup vs baseline: 1.0382x; 1.0382x over previous
#include <cuda_runtime.h>
#include <cuda_fp16.h>
#include <math.h>
#include <stdint.h>

#define BB   64
#define TT   512
#define DD   512
#define UU   1024
#define G4   4096
#define NCTA 128

__device__ float  g_xg[(size_t)BB * TT * G4];   // [t][b][4096]
__device__ __align__(16) __half g_xh[(size_t)BB * TT * DD];
__device__ __align__(16) __half g_hh[2][BB * UU];
__device__ volatile unsigned g_gen; __device__ unsigned g_pad1[31];
__device__ unsigned g_cnt;          __device__ unsigned g_pad2[31];

// ---------------- helpers ---------------------------------------------------
__device__ __forceinline__ void mma16(float c[4], unsigned a0, unsigned a1,
                                      unsigned a2, unsigned a3,
                                      unsigned b0, unsigned b1) {
    asm volatile(
        "mma.sync.aligned.m16n8k16.row.col.f32.f16.f16.f32 "
        "{%0,%1,%2,%3}, {%4,%5,%6,%7}, {%8,%9}, {%0,%1,%2,%3};"
        : "+f"(c[0]), "+f"(c[1]), "+f"(c[2]), "+f"(c[3])
        : "r"(a0), "r"(a1), "r"(a2), "r"(a3), "r"(b0), "r"(b1));
}
__device__ __forceinline__ uint4 ldsm4(unsigned addr) {
    uint4 r;
    asm volatile("ldmatrix.sync.aligned.m8n8.x4.shared.b16 {%0,%1,%2,%3}, [%4];"
                 : "=r"(r.x), "=r"(r.y), "=r"(r.z), "=r"(r.w) : "r"(addr));
    return r;
}
__device__ __forceinline__ void cp16(unsigned dst, const void* src) {
    asm volatile("cp.async.cg.shared.global [%0], [%1], 16;" :: "r"(dst), "l"(src));
}
__device__ __forceinline__ void cp_commit() {
    asm volatile("cp.async.commit_group;");
}
__device__ __forceinline__ unsigned smem_u32(const void* p) {
    unsigned a;
    asm("{ .reg .u64 t; cvta.to.shared.u64 t, %1; cvt.u32.u64 %0, t; }" : "=r"(a) : "l"(p));
    return a;
}
__device__ __forceinline__ int slot_perm(int slot5) {
    int s = slot5 >> 4, p = slot5 & 15;
    int lcp = (p < 8) ? (p >> 1) : ((p - 8) >> 1);
    int add = (p < 8) ? 0 : 2;
    return 8 * lcp + 4 * s + add + (p & 1);
}
// fast activations (R9/R10-validated)
__device__ __forceinline__ float fsig(float x) {
    float e, r;
    asm("ex2.approx.f32 %0, %1;" : "=f"(e) : "f"(-1.4426950408889634f * x));
    asm("rcp.approx.f32 %0, %1;" : "=f"(r) : "f"(1.0f + e));
    return r;
}
__device__ __forceinline__ float ftanh_(float x) {
    float e, r;
    asm("ex2.approx.f32 %0, %1;" : "=f"(e) : "f"(2.8853900817779268f * x));
    asm("rcp.approx.f32 %0, %1;" : "=f"(r) : "f"(1.0f + e));
    return 1.0f - 2.0f * r;
}

// ========================== conv_x ==========================
__global__ __launch_bounds__(256) void conv_x(const float* __restrict__ x) {
    const size_t n4 = (size_t)BB * TT * DD / 4;
    for (size_t i = (size_t)blockIdx.x * 256 + threadIdx.x; i < n4;
         i += (size_t)gridDim.x * 256) {
        float4 v = reinterpret_cast<const float4*>(x)[i];
        __half2 h01 = __floats2half2_rn(v.x, v.y);
        __half2 h23 = __floats2half2_rn(v.z, v.w);
        uint2 st;
        st.x = *reinterpret_cast<unsigned*>(&h01);
        st.y = *reinterpret_cast<unsigned*>(&h23);
        reinterpret_cast<uint2*>(g_xh)[i] = st;
    }
}

// ================= xg_kernel (R3-validated) =================
#define XG_WT_STRIDE 520
__global__ __launch_bounds__(256) void xg_kernel(
    const float* __restrict__ Wx, const float* __restrict__ bias)
{
    __shared__ __half Wt[32 * XG_WT_STRIDE];
    const int tid = threadIdx.x, warp = tid >> 5, lane = tid & 31;
    const int lr = lane >> 2, lc = lane & 3;
    const int mo = (warp & 3) * 16, no = (warp >> 2) * 16;
    const int ns = blockIdx.x & 127, mg = blockIdx.x >> 7, u0 = ns * 8;

    for (int i = tid; i < 32 * 512; i += 256) {
        int n = i & 31, slotg = i >> 5;
        int k = (slotg & ~31) + slot_perm(slotg & 31);
        int col = (n >> 3) * UU + u0 + (n & 7);
        Wt[n * XG_WT_STRIDE + slotg] = __float2half_rn(Wx[(size_t)k * G4 + col]);
    }
    __syncthreads();
    const unsigned WtB = smem_u32(Wt);
    const unsigned bAddrBase = WtB
        + (unsigned)(no + ((lane >> 4) << 3) + (lane & 7)) * (XG_WT_STRIDE * 2)
        + ((lane >> 3) & 1) * 16;
    float bv[2][2];
#pragma unroll
    for (int j = 0; j < 2; j++) {
        int cl = no + j * 8 + 2 * lc;
        int colg = (cl >> 3) * UU + u0 + (cl & 7);
        bv[j][0] = bias[colg]; bv[j][1] = bias[colg + 1];
    }
    for (int mt = 0; mt < 64; mt++) {
        const int r0 = mg * 4096 + mt * 64;
        const __half* pr0 = g_xh + (size_t)(r0 + mo + lr) * DD + 8 * lc;
        const __half* pr1 = pr0 + 8 * DD;
        float acc[2][4];
#pragma unroll
        for (int j = 0; j < 2; j++)
#pragma unroll
            for (int i = 0; i < 4; i++) acc[j][i] = 0.0f;
        uint4 a0c = *reinterpret_cast<const uint4*>(pr0);
        uint4 a1c = *reinterpret_cast<const uint4*>(pr1);
        uint4 a0n = *reinterpret_cast<const uint4*>(pr0 + 32);
        uint4 a1n = *reinterpret_cast<const uint4*>(pr1 + 32);
#pragma unroll
        for (int kc = 0; kc < 16; kc++) {
            uint4 a0f = make_uint4(0, 0, 0, 0), a1f = a0f;
            if (kc < 14) {
                a0f = *reinterpret_cast<const uint4*>(pr0 + (kc + 2) * 32);
                a1f = *reinterpret_cast<const uint4*>(pr1 + (kc + 2) * 32);
            }
            const unsigned ba = bAddrBase + kc * 64;
            uint4 B0 = ldsm4(ba);
            uint4 B1 = ldsm4(ba + 32);
            mma16(acc[0], a0c.x, a1c.x, a0c.y, a1c.y, B0.x, B0.y);
            mma16(acc[1], a0c.x, a1c.x, a0c.y, a1c.y, B0.z, B0.w);
            mma16(acc[0], a0c.z, a1c.z, a0c.w, a1c.w, B1.x, B1.y);
            mma16(acc[1], a0c.z, a1c.z, a0c.w, a1c.w, B1.z, B1.w);
            a0c = a0n; a1c = a1n; a0n = a0f; a1n = a1f;
        }
        const int rA = r0 + mo + lr, rB = rA + 8;
        const size_t row0 = (size_t)((rA & (TT - 1)) * BB + (rA >> 9)) * G4;
        const size_t row1 = (size_t)((rB & (TT - 1)) * BB + (rB >> 9)) * G4;
#pragma unroll
        for (int j = 0; j < 2; j++) {
            int cl = no + j * 8 + 2 * lc;
            int colg = (cl >> 3) * UU + u0 + (cl & 7);
            *reinterpret_cast<float2*>(&g_xg[row0 + colg]) =
                make_float2(acc[j][0] + bv[j][0], acc[j][1] + bv[j][1]);
            *reinterpret_cast<float2*>(&g_xg[row1 + colg]) =
                make_float2(acc[j][2] + bv[j][0], acc[j][3] + bv[j][1]);
        }
    }
}

// ====== persistent LSTM step kernel: 512 threads, two 8-warp teams ======
// Team T (warps 8T..8T+7) owns kc range [16T, 16T+16): stages its own
// 64KB h half (cp.async, 1 group), team-scoped bar.sync, computes with
// R10's exact 4Mx2N fragment patterns, writes partials to GkT.
#define HS_STRIDE 1032
#define WT_STRIDE 1032
#define WT_BYTES  (32 * WT_STRIDE * 2)
#define HS_BYTES  (64 * HS_STRIDE * 2)
#define SMEM_BYTES (WT_BYTES + HS_BYTES + 2 * (64 * 33 * 4) + 512 * 4)

__global__ __launch_bounds__(512) void lstm_persist(
    const float* __restrict__ Wh, const float* __restrict__ h0,
    const float* __restrict__ c0, float* __restrict__ out)
{
    extern __shared__ char smraw[];
    __half* Wt  = (__half*)smraw;
    __half* Hs  = (__half*)(smraw + WT_BYTES);
    float*  Gk0 = (float*)(smraw + WT_BYTES + HS_BYTES);
    float*  Gk1 = Gk0 + 64 * 33;
    float*  Cl  = Gk1 + 64 * 33;

    const int tid  = threadIdx.x;
    const int warp = tid >> 5, lane = tid & 31;
    const int lr = lane >> 2, lc = lane & 3;
    const int team = warp >> 3;                    // 0 or 1
    const int w4   = warp & 7;
    const int mo = (w4 & 3) * 16;
    const int no = (w4 >> 2) * 16;
    const int kco = team * 16;                     // kc base for this team
    const int u0 = blockIdx.x * 8;

    // ---- one-time init ----
    for (int i = tid; i < 32 * 1024; i += 512) {
        int n = i & 31, k = i >> 5;
        int col = (n >> 3) * UU + u0 + (n & 7);
        Wt[n * WT_STRIDE + k] = __float2half_rn(Wh[(size_t)k * G4 + col]);
    }
    for (int i = tid; i < 512; i += 512)
        Cl[i] = c0[(i >> 3) * UU + u0 + (i & 7)];
    for (int i = blockIdx.x * 512 + tid; i < BB * UU; i += NCTA * 512)
        g_hh[0][i] = __float2half_rn(h0[i]);
    __syncthreads();

    if (tid == 0) {                                // initial grid barrier
        unsigned gen = g_gen;
        __threadfence();
        if (atomicAdd(&g_cnt, 1u) == NCTA - 1u) {
            g_cnt = 0; __threadfence(); g_gen = gen + 1;
        } else {
            while (g_gen == gen) { __nanosleep(32); }
        }
        __threadfence();
    }
    __syncthreads();

    const unsigned HsB = smem_u32(Hs);
    const unsigned WtB = smem_u32(Wt);

    // R10's exact ldsm bases (per-warp fragment patterns unchanged)
    const unsigned aBase = HsB
        + (unsigned)((mo + (lane & 15)) * HS_STRIDE + (lane >> 4) * 8) * 2u;
    const unsigned bBase = WtB
        + (unsigned)((no + ((lane >> 4) << 3) + (lane & 7)) * WT_STRIDE
                     + ((lane >> 3) & 1) * 8) * 2u;
    float* GkMine = team ? Gk1 : Gk0;

    // cp roles: team's 256 threads stage the team's 64-row x 512-col half.
    const int ltid  = tid & 255;
    const int cprow = ltid >> 2, cpseg = ltid & 3;
    const unsigned cpDst = HsB
        + (unsigned)(cprow * HS_STRIDE + team * 512 + cpseg * 8) * 2u;
    const int cpSrcOff = cprow * UU + team * 512 + cpseg * 8;

    // cell roles: 512 threads, 1 elem each
    const int cm = tid >> 3, cdu = tid & 7;
    float xa[4];
#pragma unroll
    for (int g = 0; g < 4; g++)
        xa[g] = g_xg[(size_t)cm * G4 + g * UU + u0 + cdu];

    for (int t = 0; t < TT; t++) {
        const __half* __restrict__ hc = g_hh[t & 1];
        __half*       __restrict__ hn = g_hh[(t + 1) & 1];

        // ---- stage own team's h half: 16 x 16B per thread, 1 group ----
        const __half* cpSrc = hc + cpSrcOff;
#pragma unroll
        for (int i = 0; i < 16; i++)
            cp16(cpDst + i * 64, cpSrc + i * 32);
        cp_commit();
        asm volatile("cp.async.wait_group 0;");
        asm volatile("bar.sync %0, 256;" :: "r"(team + 1) : "memory");

        // ---- compute: kc in [kco, kco+16), 4 chains by kc parity ----
        float acc[2][2][4];
#pragma unroll
        for (int p = 0; p < 2; p++)
#pragma unroll
            for (int j = 0; j < 2; j++)
#pragma unroll
                for (int i = 0; i < 4; i++) acc[p][j][i] = 0.0f;
#pragma unroll
        for (int q = 0; q < 16; q++) {
            const int kc = kco + q;
            uint4 A0 = ldsm4(aBase + kc * 64);
            uint4 A1 = ldsm4(aBase + kc * 64 + 32);
            uint4 B0 = ldsm4(bBase + kc * 64);
            uint4 B1 = ldsm4(bBase + kc * 64 + 32);
            mma16(acc[0][0], A0.x, A0.y, A0.z, A0.w, B0.x, B0.y);
            mma16(acc[0][1], A0.x, A0.y, A0.z, A0.w, B0.z, B0.w);
            mma16(acc[1][0], A1.x, A1.y, A1.z, A1.w, B1.x, B1.y);
            mma16(acc[1][1], A1.x, A1.y, A1.z, A1.w, B1.z, B1.w);
        }

        // ---- partials to team buffer ----
        const int rA = mo + lr;
#pragma unroll
        for (int j = 0; j < 2; j++) {
            int cl = no + j * 8 + 2 * lc;
            GkMine[rA * 33 + cl]           = acc[0][j][0] + acc[1][j][0];
            GkMine[rA * 33 + cl + 1]       = acc[0][j][1] + acc[1][j][1];
            GkMine[(rA + 8) * 33 + cl]     = acc[0][j][2] + acc[1][j][2];
            GkMine[(rA + 8) * 33 + cl + 1] = acc[0][j][3] + acc[1][j][3];
        }
        __syncthreads();

        // ---- LSTM cell: 1 elem/thread, sum team partials + xg ----
        {
            const int gb = cm * 33 + cdu;
            float s0 = Gk0[gb]      + Gk1[gb];
            float s1 = Gk0[gb + 8]  + Gk1[gb + 8];
            float s2 = Gk0[gb + 16] + Gk1[gb + 16];
            float s3 = Gk0[gb + 24] + Gk1[gb + 24];
            float gi = fsig  (s0 + xa[0]);
            float gf = fsig  (s1 + xa[1]);
            float gg = ftanh_(s2 + xa[2]);
            float go = fsig  (s3 + xa[3]);
            int ce = cm * 8 + cdu;
            float cv = gf * Cl[ce] + gi * gg;
            Cl[ce] = cv;
            float hv = go * ftanh_(cv);
            hn[cm * UU + u0 + cdu] = __float2half_rn(hv);
            if (t == TT - 1) out[cm * UU + u0 + cdu] = hv;
        }
        __syncthreads();

        // ---- split grid barrier: arrive, prefetch xg[t+1], then wait ----
        unsigned gen;
        if (tid == 0) {
            gen = g_gen;
            __threadfence();
            if (atomicAdd(&g_cnt, 1u) == NCTA - 1u) {
                g_cnt = 0; __threadfence(); g_gen = gen + 1;
            }
        }
        if (t + 1 < TT) {
            const size_t base = (size_t)(t + 1) * BB * G4
                              + (size_t)cm * G4 + u0 + cdu;
#pragma unroll
            for (int g = 0; g < 4; g++)
                xa[g] = g_xg[base + g * UU];
        }
        if (tid == 0) {
            while (g_gen == gen) { __nanosleep(32); }
            __threadfence();
        }
        __syncthreads();
    }
}

// ============================================================================
extern "C" void kernel_launch(void* const* d_in, const int* in_sizes, int n_in,
                              void* d_out, int out_size)
{
    const float* x  = (const float*)d_in[0];
    const float* h0 = (const float*)d_in[1];
    const float* c0 = (const float*)d_in[2];
    const float* Wx = (const float*)d_in[3];
    const float* Wh = (const float*)d_in[4];
    const float* b  = (const float*)d_in[5];
    float* out = (float*)d_out;

    conv_x<<<4096, 256>>>(x);
    xg_kernel<<<1024, 256>>>(Wx, b);

    cudaFuncSetAttribute(lstm_persist, cudaFuncAttributeMaxDynamicSharedMemorySize,
                         SMEM_BYTES);
    lstm_persist<<<NCTA, 512, SMEM_BYTES>>>(Wh, h0, c0, out);

    (void)in_sizes; (void)n_in; (void)out_size;
}

// round 14
// speedup vs baseline: 1.0984x; 1.0580x over previous
#include <cuda_runtime.h>
#include <cuda_fp16.h>
#include <math.h>
#include <stdint.h>

#define BB   64
#define TT   512
#define DD   512
#define UU   1024
#define G4   4096
#define NCTA 128

__device__ float  g_xg[(size_t)BB * TT * G4];   // [t][b][4096]
__device__ __align__(16) __half g_xh[(size_t)BB * TT * DD];
__device__ __align__(16) __half g_hh[2][BB * UU];
__device__ volatile unsigned g_gen; __device__ unsigned g_pad1[31];
__device__ unsigned g_cnt;          __device__ unsigned g_pad2[31];

// ---------------- helpers ---------------------------------------------------
__device__ __forceinline__ void mma16(float c[4], unsigned a0, unsigned a1,
                                      unsigned a2, unsigned a3,
                                      unsigned b0, unsigned b1) {
    asm volatile(
        "mma.sync.aligned.m16n8k16.row.col.f32.f16.f16.f32 "
        "{%0,%1,%2,%3}, {%4,%5,%6,%7}, {%8,%9}, {%0,%1,%2,%3};"
        : "+f"(c[0]), "+f"(c[1]), "+f"(c[2]), "+f"(c[3])
        : "r"(a0), "r"(a1), "r"(a2), "r"(a3), "r"(b0), "r"(b1));
}
__device__ __forceinline__ uint4 ldsm4(unsigned addr) {
    uint4 r;
    asm volatile("ldmatrix.sync.aligned.m8n8.x4.shared.b16 {%0,%1,%2,%3}, [%4];"
                 : "=r"(r.x), "=r"(r.y), "=r"(r.z), "=r"(r.w) : "r"(addr));
    return r;
}
__device__ __forceinline__ void cp16(unsigned dst, const void* src) {
    asm volatile("cp.async.cg.shared.global [%0], [%1], 16;" :: "r"(dst), "l"(src));
}
__device__ __forceinline__ void cp_commit() {
    asm volatile("cp.async.commit_group;");
}
__device__ __forceinline__ unsigned smem_u32(const void* p) {
    unsigned a;
    asm("{ .reg .u64 t; cvta.to.shared.u64 t, %1; cvt.u32.u64 %0, t; }" : "=r"(a) : "l"(p));
    return a;
}
__device__ __forceinline__ int slot_perm(int slot5) {
    int s = slot5 >> 4, p = slot5 & 15;
    int lcp = (p < 8) ? (p >> 1) : ((p - 8) >> 1);
    int add = (p < 8) ? 0 : 2;
    return 8 * lcp + 4 * s + add + (p & 1);
}
// fast activations (R9/R10-validated)
__device__ __forceinline__ float fsig(float x) {
    float e, r;
    asm("ex2.approx.f32 %0, %1;" : "=f"(e) : "f"(-1.4426950408889634f * x));
    asm("rcp.approx.f32 %0, %1;" : "=f"(r) : "f"(1.0f + e));
    return r;
}
__device__ __forceinline__ float ftanh_(float x) {
    float e, r;
    asm("ex2.approx.f32 %0, %1;" : "=f"(e) : "f"(2.8853900817779268f * x));
    asm("rcp.approx.f32 %0, %1;" : "=f"(r) : "f"(1.0f + e));
    return 1.0f - 2.0f * r;
}

// ========================== conv_x ==========================
__global__ __launch_bounds__(256) void conv_x(const float* __restrict__ x) {
    const size_t n4 = (size_t)BB * TT * DD / 4;
    for (size_t i = (size_t)blockIdx.x * 256 + threadIdx.x; i < n4;
         i += (size_t)gridDim.x * 256) {
        float4 v = reinterpret_cast<const float4*>(x)[i];
        __half2 h01 = __floats2half2_rn(v.x, v.y);
        __half2 h23 = __floats2half2_rn(v.z, v.w);
        uint2 st;
        st.x = *reinterpret_cast<unsigned*>(&h01);
        st.y = *reinterpret_cast<unsigned*>(&h23);
        reinterpret_cast<uint2*>(g_xh)[i] = st;
    }
}

// ====== xg_kernel: 128 gate-cols per CTA (32 units), 256 CTAs ======
#define XG_WS 520                            // fp16 slots per n-row (512+8)
#define XG_SMEM (128 * XG_WS * 2)            // 133120 B

__global__ __launch_bounds__(256) void xg_kernel(
    const float* __restrict__ Wx, const float* __restrict__ bias)
{
    extern __shared__ __half Wt[];
    const int tid = threadIdx.x, warp = tid >> 5, lane = tid & 31;
    const int lr = lane >> 2, lc = lane & 3;
    const int mo = (warp & 3) * 16, noW = (warp >> 2) * 16;
    const int ns = blockIdx.x & 31, mg = blockIdx.x >> 5;
    const int v0 = ns * 32;                  // first unit of 32

    // Wt[n][slot]: n = gate*32 + unit (128 rows), k-permuted slots
    for (int i = tid; i < 128 * 512; i += 256) {
        int n = i & 127, slotg = i >> 7;
        int k = (slotg & ~31) + slot_perm(slotg & 31);
        int col = (n >> 5) * UU + v0 + (n & 31);
        Wt[n * XG_WS + slotg] = __float2half_rn(Wx[(size_t)k * G4 + col]);
    }
    __syncthreads();
    const unsigned WtB = smem_u32(Wt);
    const unsigned bAB = WtB
        + (unsigned)(noW + ((lane >> 4) << 3) + (lane & 7)) * (XG_WS * 2)
        + ((lane >> 3) & 1) * 16;

    float bv[4][2][2];
#pragma unroll
    for (int nh = 0; nh < 4; nh++)
#pragma unroll
        for (int j = 0; j < 2; j++) {
            int cl = noW + nh * 32 + j * 8 + 2 * lc;
            int colg = (cl >> 5) * UU + v0 + (cl & 31);
            bv[nh][j][0] = bias[colg]; bv[nh][j][1] = bias[colg + 1];
        }

    for (int mt = 0; mt < 64; mt++) {
        const int r0 = mg * 4096 + mt * 64;
        const __half* pr0 = g_xh + (size_t)(r0 + mo + lr) * DD + 8 * lc;
        const __half* pr1 = pr0 + 8 * DD;

        float acc[4][2][4];
#pragma unroll
        for (int nh = 0; nh < 4; nh++)
#pragma unroll
            for (int j = 0; j < 2; j++)
#pragma unroll
                for (int i = 0; i < 4; i++) acc[nh][j][i] = 0.0f;

        uint4 a0c = *reinterpret_cast<const uint4*>(pr0);
        uint4 a1c = *reinterpret_cast<const uint4*>(pr1);
        uint4 a0n = *reinterpret_cast<const uint4*>(pr0 + 32);
        uint4 a1n = *reinterpret_cast<const uint4*>(pr1 + 32);
#pragma unroll
        for (int kc = 0; kc < 16; kc++) {
            uint4 a0f = make_uint4(0, 0, 0, 0), a1f = a0f;
            if (kc < 14) {
                a0f = *reinterpret_cast<const uint4*>(pr0 + (kc + 2) * 32);
                a1f = *reinterpret_cast<const uint4*>(pr1 + (kc + 2) * 32);
            }
#pragma unroll
            for (int nh = 0; nh < 4; nh++) {
                const unsigned ba = bAB + nh * (32 * XG_WS * 2) + kc * 64;
                uint4 B0 = ldsm4(ba);
                uint4 B1 = ldsm4(ba + 32);
                mma16(acc[nh][0], a0c.x, a1c.x, a0c.y, a1c.y, B0.x, B0.y);
                mma16(acc[nh][1], a0c.x, a1c.x, a0c.y, a1c.y, B0.z, B0.w);
                mma16(acc[nh][0], a0c.z, a1c.z, a0c.w, a1c.w, B1.x, B1.y);
                mma16(acc[nh][1], a0c.z, a1c.z, a0c.w, a1c.w, B1.z, B1.w);
            }
            a0c = a0n; a1c = a1n; a0n = a0f; a1n = a1f;
        }

        const int rA = r0 + mo + lr, rB = rA + 8;
        const size_t row0 = (size_t)((rA & (TT - 1)) * BB + (rA >> 9)) * G4;
        const size_t row1 = (size_t)((rB & (TT - 1)) * BB + (rB >> 9)) * G4;
#pragma unroll
        for (int nh = 0; nh < 4; nh++)
#pragma unroll
            for (int j = 0; j < 2; j++) {
                int cl = noW + nh * 32 + j * 8 + 2 * lc;
                int colg = (cl >> 5) * UU + v0 + (cl & 31);
                __stcs(reinterpret_cast<float2*>(&g_xg[row0 + colg]),
                       make_float2(acc[nh][j][0] + bv[nh][j][0],
                                   acc[nh][j][1] + bv[nh][j][1]));
                __stcs(reinterpret_cast<float2*>(&g_xg[row1 + colg]),
                       make_float2(acc[nh][j][2] + bv[nh][j][0],
                                   acc[nh][j][3] + bv[nh][j][1]));
            }
    }
}

// ============== persistent LSTM step kernel (R10 verbatim — 4903us) ==============
#define HS_STRIDE 1032
#define WT_STRIDE 1032
#define WT_BYTES  (32 * WT_STRIDE * 2)
#define HS_BYTES  (64 * HS_STRIDE * 2)
#define SMEM_BYTES (WT_BYTES + HS_BYTES + 64 * 33 * 4 + 512 * 4)

__global__ __launch_bounds__(256) void lstm_persist(
    const float* __restrict__ Wh, const float* __restrict__ h0,
    const float* __restrict__ c0, float* __restrict__ out)
{
    extern __shared__ char smraw[];
    __half* Wt = (__half*)smraw;
    __half* Hs = (__half*)(smraw + WT_BYTES);
    float*  Gs = (float*)(smraw + WT_BYTES + HS_BYTES);
    float*  Cl = Gs + 64 * 33;

    const int tid  = threadIdx.x;
    const int warp = tid >> 5, lane = tid & 31;
    const int lr = lane >> 2, lc = lane & 3;
    const int mo = (warp & 3) * 16;
    const int no = (warp >> 2) * 16;
    const int u0 = blockIdx.x * 8;

    for (int i = tid; i < 32 * 1024; i += 256) {
        int n = i & 31, k = i >> 5;
        int col = (n >> 3) * UU + u0 + (n & 7);
        Wt[n * WT_STRIDE + k] = __float2half_rn(Wh[(size_t)k * G4 + col]);
    }
    for (int i = tid; i < 512; i += 256)
        Cl[i] = c0[(i >> 3) * UU + u0 + (i & 7)];
    for (int i = blockIdx.x * 256 + tid; i < BB * UU; i += NCTA * 256)
        g_hh[0][i] = __float2half_rn(h0[i]);
    __syncthreads();

    if (tid == 0) {
        unsigned gen = g_gen;
        __threadfence();
        if (atomicAdd(&g_cnt, 1u) == NCTA - 1u) {
            g_cnt = 0; __threadfence(); g_gen = gen + 1;
        } else {
            while (g_gen == gen) { __nanosleep(32); }
        }
        __threadfence();
    }
    __syncthreads();

    const unsigned HsB = smem_u32(Hs);
    const unsigned WtB = smem_u32(Wt);

    const unsigned aBase = HsB
        + (unsigned)((mo + (lane & 15)) * HS_STRIDE + (lane >> 4) * 8) * 2u;
    const unsigned bBase = WtB
        + (unsigned)((no + ((lane >> 4) << 3) + (lane & 7)) * WT_STRIDE
                     + ((lane >> 3) & 1) * 8) * 2u;

    const int cprow = tid >> 2, cpseg = tid & 3;
    const unsigned cpDst = HsB + (unsigned)(cprow * HS_STRIDE + cpseg * 8) * 2u;

    float2 xv[2][2];
#pragma unroll
    for (int j = 0; j < 2; j++) {
        int cl = no + j * 8 + 2 * lc;
        int colg = (cl >> 3) * UU + u0 + (cl & 7);
        xv[j][0] = *reinterpret_cast<const float2*>(&g_xg[(size_t)(mo + lr) * G4 + colg]);
        xv[j][1] = *reinterpret_cast<const float2*>(&g_xg[(size_t)(mo + lr + 8) * G4 + colg]);
    }

    for (int t = 0; t < TT; t++) {
        const __half* __restrict__ hc = g_hh[t & 1];
        __half*       __restrict__ hn = g_hh[(t + 1) & 1];

        const __half* cpSrc = hc + (size_t)cprow * UU + cpseg * 8;
#pragma unroll
        for (int kc = 0; kc < 32; kc++) {
            cp16(cpDst + kc * 64, cpSrc + kc * 32);
            cp_commit();
        }

        float acc[2][2][4];
#pragma unroll
        for (int p = 0; p < 2; p++)
#pragma unroll
            for (int j = 0; j < 2; j++)
#pragma unroll
                for (int i = 0; i < 4; i++) acc[p][j][i] = 0.0f;

        asm volatile("cp.async.wait_group 16;");
        __syncthreads();
#pragma unroll
        for (int kc = 0; kc < 16; kc++) {
            uint4 A0 = ldsm4(aBase + kc * 64);
            uint4 A1 = ldsm4(aBase + kc * 64 + 32);
            uint4 B0 = ldsm4(bBase + kc * 64);
            uint4 B1 = ldsm4(bBase + kc * 64 + 32);
            mma16(acc[0][0], A0.x, A0.y, A0.z, A0.w, B0.x, B0.y);
            mma16(acc[0][1], A0.x, A0.y, A0.z, A0.w, B0.z, B0.w);
            mma16(acc[1][0], A1.x, A1.y, A1.z, A1.w, B1.x, B1.y);
            mma16(acc[1][1], A1.x, A1.y, A1.z, A1.w, B1.z, B1.w);
        }
        asm volatile("cp.async.wait_group 0;");
        __syncthreads();
#pragma unroll
        for (int kc = 16; kc < 32; kc++) {
            uint4 A0 = ldsm4(aBase + kc * 64);
            uint4 A1 = ldsm4(aBase + kc * 64 + 32);
            uint4 B0 = ldsm4(bBase + kc * 64);
            uint4 B1 = ldsm4(bBase + kc * 64 + 32);
            mma16(acc[0][0], A0.x, A0.y, A0.z, A0.w, B0.x, B0.y);
            mma16(acc[0][1], A0.x, A0.y, A0.z, A0.w, B0.z, B0.w);
            mma16(acc[1][0], A1.x, A1.y, A1.z, A1.w, B1.x, B1.y);
            mma16(acc[1][1], A1.x, A1.y, A1.z, A1.w, B1.z, B1.w);
        }

        const int rA = mo + lr;
#pragma unroll
        for (int j = 0; j < 2; j++) {
            int cl = no + j * 8 + 2 * lc;
            Gs[rA * 33 + cl]           = acc[0][j][0] + acc[1][j][0] + xv[j][0].x;
            Gs[rA * 33 + cl + 1]       = acc[0][j][1] + acc[1][j][1] + xv[j][0].y;
            Gs[(rA + 8) * 33 + cl]     = acc[0][j][2] + acc[1][j][2] + xv[j][1].x;
            Gs[(rA + 8) * 33 + cl + 1] = acc[0][j][3] + acc[1][j][3] + xv[j][1].y;
        }
        __syncthreads();

#pragma unroll
        for (int q = 0; q < 2; q++) {
            int e  = tid + q * 256;
            int m  = e >> 3, du = e & 7;
            float gi = fsig  (Gs[m * 33 + 0 * 8 + du]);
            float gf = fsig  (Gs[m * 33 + 1 * 8 + du]);
            float gg = ftanh_(Gs[m * 33 + 2 * 8 + du]);
            float go = fsig  (Gs[m * 33 + 3 * 8 + du]);
            float cv = gf * Cl[e] + gi * gg;
            Cl[e] = cv;
            float hv = go * ftanh_(cv);
            hn[m * UU + u0 + du] = __float2half_rn(hv);
            if (t == TT - 1) out[m * UU + u0 + du] = hv;
        }
        __syncthreads();

        unsigned gen;
        if (tid == 0) {
            gen = g_gen;
            __threadfence();
            if (atomicAdd(&g_cnt, 1u) == NCTA - 1u) {
                g_cnt = 0; __threadfence(); g_gen = gen + 1;
            }
        }
        if (t + 1 < TT) {
            const size_t base = (size_t)(t + 1) * BB * G4;
#pragma unroll
            for (int j = 0; j < 2; j++) {
                int cl = no + j * 8 + 2 * lc;
                int colg = (cl >> 3) * UU + u0 + (cl & 7);
                xv[j][0] = *reinterpret_cast<const float2*>(
                    &g_xg[base + (size_t)(mo + lr) * G4 + colg]);
                xv[j][1] = *reinterpret_cast<const float2*>(
                    &g_xg[base + (size_t)(mo + lr + 8) * G4 + colg]);
            }
        }
        if (tid == 0) {
            while (g_gen == gen) { __nanosleep(32); }
            __threadfence();
        }
        __syncthreads();
    }
}

// ============================================================================
extern "C" void kernel_launch(void* const* d_in, const int* in_sizes, int n_in,
                              void* d_out, int out_size)
{
    const float* x  = (const float*)d_in[0];
    const float* h0 = (const float*)d_in[1];
    const float* c0 = (const float*)d_in[2];
    const float* Wx = (const float*)d_in[3];
    const float* Wh = (const float*)d_in[4];
    const float* b  = (const float*)d_in[5];
    float* out = (float*)d_out;

    conv_x<<<4096, 256>>>(x);

    cudaFuncSetAttribute(xg_kernel, cudaFuncAttributeMaxDynamicSharedMemorySize,
                         XG_SMEM);
    xg_kernel<<<256, 256, XG_SMEM>>>(Wx, b);

    cudaFuncSetAttribute(lstm_persist, cudaFuncAttributeMaxDynamicSharedMemorySize,
                         SMEM_BYTES);
    lstm_persist<<<NCTA, 256, SMEM_BYTES>>>(Wh, h0, c0, out);

    (void)in_sizes; (void)n_in; (void)out_size;
}